// round 17
// baseline (speedup 1.0000x reference)
#include <cuda_runtime.h>
#include <cuda_fp16.h>
#include <cstdint>

typedef unsigned int u32;
typedef unsigned long long u64;

// Problem constants (x[N,256], W[256,128], b[128], out[N,64])
#define D_IN   256
#define C_OUT  128
#define EPSV   1e-6f
#define TM     128
#define THREADS 256
#define MAXB   4096
#define NPART  1088          // 1024 VtZ + 32 sumU + 32 sumV
#define KC     64            // K elems per chunk
#define NCH    4             // 256 / 64
#define GRIDP  296           // persistent grid: 2 CTAs x 148 SMs

// fp16 tile 128 x 64, padded row stride 72 elems (144 B) -> conflict-free ldmatrix
#define AST      72
#define RB       (AST * 2)           // row bytes = 144
#define TILE_B   (128 * RB)          // 18432 B
#define XOFF     (4 * TILE_B)        // W: 4 chunks staged once per CTA
#define DSM_B    (XOFF + 2 * TILE_B) // 110592 B -> 2 CTAs/SM

// epilogue scratch aliases the x double-buffer region (mainloop finished):
//   vs16/zs16: fp16 [128][40] each (80 B rows, conflict-free ldmatrix.trans)
#define VZROW_B  80

__device__ float g_part[(size_t)NPART * MAXB];
__device__ float g_red[NPART];
__device__ __half g_Wh[C_OUT * D_IN];                 // [n][k] K-major fp16
__device__ __half g_Uh[(size_t)MAXB * TM * 32];       // U staged fp16 [row][32]

// ---------------------------------------------------------------------------
// helpers
// ---------------------------------------------------------------------------
__device__ __forceinline__ u32 smem_u32(const void* p) {
    u32 a; asm("{ .reg .u64 t; cvta.to.shared.u64 t, %1; cvt.u32.u64 %0, t; }"
               : "=r"(a) : "l"(p));
    return a;
}
__device__ __forceinline__ void sts8(u32 addr, u32 a, u32 b) {
    asm volatile("st.shared.v2.u32 [%0], {%1,%2};" :: "r"(addr), "r"(a), "r"(b) : "memory");
}
__device__ __forceinline__ void sts16(u32 addr, float4 v) {
    asm volatile("st.shared.v4.b32 [%0], {%1,%2,%3,%4};"
                 :: "r"(addr), "f"(v.x), "f"(v.y), "f"(v.z), "f"(v.w) : "memory");
}
__device__ __forceinline__ void ldm_x4(u32 a, u32& r0, u32& r1, u32& r2, u32& r3) {
    asm volatile("ldmatrix.sync.aligned.m8n8.x4.shared.b16 {%0,%1,%2,%3}, [%4];"
                 : "=r"(r0), "=r"(r1), "=r"(r2), "=r"(r3) : "r"(a));
}
__device__ __forceinline__ void ldm_x4t(u32 a, u32& r0, u32& r1, u32& r2, u32& r3) {
    asm volatile("ldmatrix.sync.aligned.m8n8.x4.trans.shared.b16 {%0,%1,%2,%3}, [%4];"
                 : "=r"(r0), "=r"(r1), "=r"(r2), "=r"(r3) : "r"(a));
}
__device__ __forceinline__ void ldm_x2t(u32 a, u32& r0, u32& r1) {
    asm volatile("ldmatrix.sync.aligned.m8n8.x2.trans.shared.b16 {%0,%1}, [%2];"
                 : "=r"(r0), "=r"(r1) : "r"(a));
}
__device__ __forceinline__ void mma16816(float& c0, float& c1, float& c2, float& c3,
                                         u32 a0, u32 a1, u32 a2, u32 a3,
                                         u32 b0, u32 b1) {
    asm volatile("mma.sync.aligned.m16n8k16.row.col.f32.f16.f16.f32 "
                 "{%0,%1,%2,%3}, {%4,%5,%6,%7}, {%8,%9}, {%0,%1,%2,%3};"
                 : "+f"(c0), "+f"(c1), "+f"(c2), "+f"(c3)
                 : "r"(a0), "r"(a1), "r"(a2), "r"(a3), "r"(b0), "r"(b1));
}
__device__ __forceinline__ u32 h2(float lo, float hi) {
    u32 r; asm("cvt.rn.f16x2.f32 %0, %1, %2;" : "=r"(r) : "f"(hi), "f"(lo)); return r;
}
// named pair barrier: warps {p, p+4} (64 threads), barrier id p+1
__device__ __forceinline__ void barp(int p) {
    asm volatile("bar.sync %0, 64;" :: "r"(p + 1) : "memory");
}

// ---------------------------------------------------------------------------
// dummy kernels: rotate the ncu -s 5 capture slot onto pass1
// ---------------------------------------------------------------------------
__global__ void dummy1_kernel() {}
__global__ void dummy2_kernel() {}

// ---------------------------------------------------------------------------
// W convert prologue: g_Wh[n][k] = fp16(W[k][n])
// ---------------------------------------------------------------------------
__global__ void wconv_kernel(const float* __restrict__ W) {
    int idx = blockIdx.x * blockDim.x + threadIdx.x;
    if (idx >= D_IN * C_OUT) return;
    int k = idx / C_OUT, n = idx % C_OUT;
    g_Wh[n * D_IN + k] = __float2half_rn(W[idx]);
}

// ---------------------------------------------------------------------------
// Pass 1 (persistent): X = relu(x@W + b) via fp16 mma.sync.
// 296 CTAs loop over row-tiles. W staged ONCE per CTA; x double-buffered smem.
// PAIR-LOCAL x staging: warp pair {wm, wm+4} owns x rows [32wm, 32wm+32) and
// is the ONLY reader of those rows -> mainloop uses 64-thread named barriers
// (bar.sync wm+1, 64) instead of full __syncthreads (3 full syncs/tile left).
// Next-chunk LDGs interleaved into the MMA ks-loop; B-frags preloaded 1 ahead.
// VtZ: per-warp m16 x n8 block in persistent fp32 regs across all tiles.
// ---------------------------------------------------------------------------
__global__ __launch_bounds__(THREADS, 2)
void pass1_kernel(const float* __restrict__ x, const float* __restrict__ b,
                  float* __restrict__ out, int N, int nb)
{
    extern __shared__ __align__(16) char dsm[];
    __shared__ float s_b[C_OUT];
    __shared__ float redU[128], redV[128];

    const int tid = threadIdx.x, lane = tid & 31, wid = tid >> 5;
    const int wm = wid & 3, wn = wid >> 2;     // warp tile coords (GEMM phase)
    const int half = wn;                       // pair half (0 or 1)
    const u32 base = smem_u32(dsm);

    if (tid < C_OUT) s_b[tid] = b[tid];

    // ---- stage all of W (fp16, 4 chunks) once ----
#pragma unroll
    for (int q = 0; q < 16; q++) {
        int f = tid + 256 * q;                 // 4096 float4 units
        int n = f >> 5;                        // 0..127
        int unit = f & 31;                     // 32 x 16B per n-row
        int ch = unit >> 3, ko = (unit & 7) * 8;
        float4 v = *(const float4*)(g_Wh + n * D_IN + unit * 8);
        sts16(base + ch * TILE_B + n * RB + ko * 2, v);
    }
    __syncthreads();                           // W visible to all warps

    char* vzbase = dsm + XOFF;                 // vs16/zs16 scratch (aliases x bufs)

    u32 xh[16];   // 8 float4 -> 16 f16x2

    // pair-local staging: this thread's slot q covers row 32*wm + 16*half + (f>>4)
    auto ldg_part = [&](int r0, int c, int q) {
        const float* xp = x + (size_t)r0 * D_IN + c * KC;
        int f = lane + 32 * q;                 // 0..255 within this warp's 16 rows
        int row = wm * 32 + half * 16 + (f >> 4);
        int c4 = (f & 15) * 4;
        float4 v = make_float4(0.f, 0.f, 0.f, 0.f);
        if (r0 + row < N) v = *(const float4*)(xp + (size_t)row * D_IN + c4);
        xh[2 * q]     = h2(v.x, v.y);
        xh[2 * q + 1] = h2(v.z, v.w);
    };
    auto ldg_all = [&](int r0, int c) {
#pragma unroll
        for (int q = 0; q < 8; q++) ldg_part(r0, c, q);
    };
    auto sts = [&](u32 xbuf) {
        const u32 xb = base + XOFF + xbuf;
#pragma unroll
        for (int q = 0; q < 8; q++) {
            int f = lane + 32 * q;
            int row = wm * 32 + half * 16 + (f >> 4);
            int c4 = (f & 15) * 4;
            sts8(xb + row * RB + c4 * 2, xh[2 * q], xh[2 * q + 1]);
        }
    };

    float acc[2][8][4];

    // MMA over chunk c; if ld_c >= 0, interleave 2 LDG.128/ks of chunk ld_c.
    // B fragments preloaded one np-block ahead.
    auto mma_chunk = [&](int c, u32 xbuf, int r0, int ld_c) {
        const u32 ab = base + XOFF + xbuf;
        const u32 bb = base + c * TILE_B;
        const u32 aoff = (wm * 32 + (lane & 15)) * RB + (lane >> 4) * 16;
        const u32 boff = (wn * 64 + (lane & 7) + ((lane >> 4) & 1) * 8) * RB
                       + ((lane >> 3) & 1) * 16;
#pragma unroll
        for (int ks = 0; ks < 4; ks++) {
            if (ld_c >= 0) {
                ldg_part(r0, ld_c, 2 * ks);
                ldg_part(r0, ld_c, 2 * ks + 1);
            }
            u32 a[2][4];
            ldm_x4(ab + aoff + ks * 32,           a[0][0], a[0][1], a[0][2], a[0][3]);
            ldm_x4(ab + aoff + 16 * RB + ks * 32, a[1][0], a[1][1], a[1][2], a[1][3]);
            u32 bn0, bn1, bn2, bn3;
            ldm_x4(bb + boff + ks * 32, bn0, bn1, bn2, bn3);   // np = 0
#pragma unroll
            for (int np = 0; np < 4; np++) {
                u32 bc0 = bn0, bc1 = bn1, bc2 = bn2, bc3 = bn3;
                if (np < 3)
                    ldm_x4(bb + boff + (np + 1) * 16 * RB + ks * 32,
                           bn0, bn1, bn2, bn3);
#pragma unroll
                for (int mt = 0; mt < 2; mt++) {
                    mma16816(acc[mt][2 * np][0], acc[mt][2 * np][1],
                             acc[mt][2 * np][2], acc[mt][2 * np][3],
                             a[mt][0], a[mt][1], a[mt][2], a[mt][3], bc0, bc1);
                    mma16816(acc[mt][2 * np + 1][0], acc[mt][2 * np + 1][1],
                             acc[mt][2 * np + 1][2], acc[mt][2 * np + 1][3],
                             a[mt][0], a[mt][1], a[mt][2], a[mt][3], bc2, bc3);
                }
            }
        }
    };

    // VtZ persistent accumulators: warp owns m16 block mb, n8 block nbk
    const int mb  = (wid & 1) * 16;
    const int nbk = (wid >> 1) * 8;
    float pc0 = 0.f, pc1 = 0.f, pc2 = 0.f, pc3 = 0.f;

    // prefetch chunk 0 of first tile
    if ((int)blockIdx.x < nb) ldg_all(blockIdx.x * TM, 0);

    for (int tile = blockIdx.x; tile < nb; tile += GRIDP) {
        const int r0 = tile * TM;

#pragma unroll
        for (int mt = 0; mt < 2; mt++)
#pragma unroll
            for (int nt = 0; nt < 8; nt++)
#pragma unroll
                for (int q = 0; q < 4; q++) acc[mt][nt][q] = 0.f;

        sts(0);
        barp(wm);
#pragma unroll
        for (int c = 0; c < NCH; c++) {
            mma_chunk(c, (c & 1) * TILE_B, r0, c < NCH - 1 ? c + 1 : -1);
            if (c < NCH - 1) {
                sts(((c + 1) & 1) * TILE_B);
                barp(wm);
            }
        }
        __syncthreads();   // ALL warps done with x bufs before vs/zs epilogue

        // prefetch next tile's chunk 0 behind the epilogue
        if (tile + GRIDP < nb) ldg_all((tile + GRIDP) * TM, 0);

        // ---- epilogue: bias/relu, U->g_Uh, T->out, V/Z->smem fp16 ----
#pragma unroll
        for (int nt = 0; nt < 8; nt++) {
            const int colb = wn * 64 + nt * 8 + (lane & 3) * 2;
            const float b0 = s_b[colb], b1 = s_b[colb + 1];
            float v[2][4];
            int rl[2];
#pragma unroll
            for (int mt = 0; mt < 2; mt++) {
                rl[mt] = wm * 32 + mt * 16 + (lane >> 2);
                const bool o1 = (r0 + rl[mt]) < N, o2 = (r0 + rl[mt] + 8) < N;
                v[mt][0] = o1 ? fmaxf(acc[mt][nt][0] + b0, 0.f) : 0.f;
                v[mt][1] = o1 ? fmaxf(acc[mt][nt][1] + b1, 0.f) : 0.f;
                v[mt][2] = o2 ? fmaxf(acc[mt][nt][2] + b0, 0.f) : 0.f;
                v[mt][3] = o2 ? fmaxf(acc[mt][nt][3] + b1, 0.f) : 0.f;
            }
            if (wn == 0) {
                if (nt < 4) {
                    // U -> g_Uh (fp16) cols 0..31
#pragma unroll
                    for (int mt = 0; mt < 2; mt++) {
                        if (r0 + rl[mt] < N)
                            *(u32*)(g_Uh + (size_t)(r0 + rl[mt]) * 32 + colb) =
                                h2(v[mt][0], v[mt][1]);
                        if (r0 + rl[mt] + 8 < N)
                            *(u32*)(g_Uh + (size_t)(r0 + rl[mt] + 8) * 32 + colb) =
                                h2(v[mt][2], v[mt][3]);
                    }
                    float s0 = v[0][0] + v[0][2] + v[1][0] + v[1][2];
                    float s1 = v[0][1] + v[0][3] + v[1][1] + v[1][3];
                    s0 += __shfl_down_sync(0xffffffffu, s0, 16);
                    s0 += __shfl_down_sync(0xffffffffu, s0, 8);
                    s0 += __shfl_down_sync(0xffffffffu, s0, 4);
                    s1 += __shfl_down_sync(0xffffffffu, s1, 16);
                    s1 += __shfl_down_sync(0xffffffffu, s1, 8);
                    s1 += __shfl_down_sync(0xffffffffu, s1, 4);
                    if (lane < 4) {
                        redU[wm * 32 + nt * 8 + lane * 2]     = s0;
                        redU[wm * 32 + nt * 8 + lane * 2 + 1] = s1;
                    }
                } else {
                    // V -> vs16 fp16
                    const int vc = colb - 32;
#pragma unroll
                    for (int mt = 0; mt < 2; mt++) {
                        *(u32*)(vzbase + rl[mt] * VZROW_B + vc * 2) =
                            h2(v[mt][0], v[mt][1]);
                        *(u32*)(vzbase + (rl[mt] + 8) * VZROW_B + vc * 2) =
                            h2(v[mt][2], v[mt][3]);
                    }
                    float s0 = v[0][0] + v[0][2] + v[1][0] + v[1][2];
                    float s1 = v[0][1] + v[0][3] + v[1][1] + v[1][3];
                    s0 += __shfl_down_sync(0xffffffffu, s0, 16);
                    s0 += __shfl_down_sync(0xffffffffu, s0, 8);
                    s0 += __shfl_down_sync(0xffffffffu, s0, 4);
                    s1 += __shfl_down_sync(0xffffffffu, s1, 16);
                    s1 += __shfl_down_sync(0xffffffffu, s1, 8);
                    s1 += __shfl_down_sync(0xffffffffu, s1, 4);
                    if (lane < 4) {
                        redV[wm * 32 + (nt - 4) * 8 + lane * 2]     = s0;
                        redV[wm * 32 + (nt - 4) * 8 + lane * 2 + 1] = s1;
                    }
                }
            } else {
                if (nt < 4) {
                    // Z -> zs16 fp16
                    const int zc = colb - 64;
#pragma unroll
                    for (int mt = 0; mt < 2; mt++) {
                        *(u32*)(vzbase + 128 * VZROW_B + rl[mt] * VZROW_B + zc * 2) =
                            h2(v[mt][0], v[mt][1]);
                        *(u32*)(vzbase + 128 * VZROW_B + (rl[mt] + 8) * VZROW_B + zc * 2) =
                            h2(v[mt][2], v[mt][3]);
                    }
                } else {
                    // T -> out[:, colb-64] (cols 32..63)
                    const int tc = colb - 64;
#pragma unroll
                    for (int mt = 0; mt < 2; mt++) {
                        if (r0 + rl[mt] < N)
                            *(float2*)(out + (size_t)(r0 + rl[mt]) * 64 + tc) =
                                make_float2(v[mt][0], v[mt][1]);
                        if (r0 + rl[mt] + 8 < N)
                            *(float2*)(out + (size_t)(r0 + rl[mt] + 8) * 64 + tc) =
                                make_float2(v[mt][2], v[mt][3]);
                    }
                }
            }
        }
        __syncthreads();

        // ---- VtZ: warp accumulates its m16 x n8 block over all k=128 ----
        {
            const u32 vb = base + XOFF;
            const u32 zb = vb + 128 * VZROW_B;
            const u32 arow = (lane & 7) + ((lane >> 4) & 1) * 8;
            const u32 acol = (u32)(mb * 2) + ((lane >> 3) & 1) * 16;
            const u32 brow = (lane & 7) + ((lane >> 3) & 1) * 8;
#pragma unroll
            for (int k = 0; k < 8; k++) {
                u32 A0, A1, A2, A3, B0, B1;
                ldm_x4t(vb + (k * 16 + arow) * VZROW_B + acol, A0, A1, A2, A3);
                ldm_x2t(zb + (k * 16 + brow) * VZROW_B + (u32)(nbk * 2), B0, B1);
                mma16816(pc0, pc1, pc2, pc3, A0, A1, A2, A3, B0, B1);
            }
        }
        // colsum partials (per tile)
        if (tid < 32) {
            float s = redU[tid] + redU[32 + tid] + redU[64 + tid] + redU[96 + tid];
            g_part[(size_t)(1024 + tid) * MAXB + tile] = s;
        } else if (tid < 64) {
            int t = tid - 32;
            float s = redV[t] + redV[32 + t] + redV[64 + t] + redV[96 + t];
            g_part[(size_t)(1056 + t) * MAXB + tile] = s;
        }
        __syncthreads();   // vs/zs/red reads done before next tile overwrites
    }

    // ---- final VtZ write: one store per warp block, column = blockIdx ----
    {
        const int m0 = mb + (lane >> 2);
        const int nc = nbk + (lane & 3) * 2;
        g_part[(size_t)(m0 * 32 + nc) * MAXB + blockIdx.x]           = pc0;
        g_part[(size_t)(m0 * 32 + nc + 1) * MAXB + blockIdx.x]       = pc1;
        g_part[(size_t)((m0 + 8) * 32 + nc) * MAXB + blockIdx.x]     = pc2;
        g_part[(size_t)((m0 + 8) * 32 + nc + 1) * MAXB + blockIdx.x] = pc3;
    }
}

// ---------------------------------------------------------------------------
// Pass 2: deterministic reduction (one warp per output, fixed shuffle tree).
// VtZ outputs (0..1023) reduce over np CTA columns; colsums over nb tiles.
// ---------------------------------------------------------------------------
__global__ void reduce_kernel(int nvtz, int nb)
{
    int gtid = blockIdx.x * blockDim.x + threadIdx.x;
    int warp = gtid >> 5, lane = gtid & 31;
    if (warp >= NPART) return;
    const int cnt = (warp < 1024) ? nvtz : nb;
    const float* p = g_part + (size_t)warp * MAXB;
    float s = 0.f;
    for (int bq = lane; bq < cnt; bq += 32) s += p[bq];
#pragma unroll
    for (int off = 16; off; off >>= 1)
        s += __shfl_down_sync(0xffffffffu, s, off);
    if (lane == 0) g_red[warp] = s;
}

// ---------------------------------------------------------------------------
// Pass 3 (tensor): out[:,0:32] = U @ (VtZ * D).
// U read as fp16 from g_Uh; M^T fp16 B-frags in registers.
// Each warp handles FOUR independent 16-row tiles (high MLP).
// ---------------------------------------------------------------------------
__global__ __launch_bounds__(THREADS)
void pass3_kernel(float* __restrict__ out, int N)
{
    __shared__ __align__(16) __half Mt[32 * 40];   // [j][k], row stride 80 B
    __shared__ float sD;
    const int tid = threadIdx.x, lane = tid & 31, wid = tid >> 5;

    if (tid < 32) {
        float p = g_red[1024 + tid] * g_red[1056 + tid];
#pragma unroll
        for (int off = 16; off; off >>= 1)
            p += __shfl_down_sync(0xffffffffu, p, off);
        if (tid == 0) sD = 1.0f / (p / (float)N + EPSV);
    }
    __syncthreads();
    const float D = sD;
#pragma unroll
    for (int q = tid; q < 512; q += THREADS) {
        int j = q >> 4, kk = (q & 15) * 2;
        u32 val = h2(g_red[kk * 32 + j] * D, g_red[(kk + 1) * 32 + j] * D);
        *(u32*)((char*)Mt + j * 80 + kk * 2) = val;
    }
    __syncthreads();

    const u32 mtb = smem_u32(Mt);
    const u32 boffb = (u32)(((lane & 7) + ((lane >> 4) & 1) * 8) * 80
                            + ((lane >> 3) & 1) * 16);
    u32 Bf[4][2][2];
#pragma unroll
    for (int np = 0; np < 2; np++)
#pragma unroll
        for (int ks = 0; ks < 2; ks++) {
            u32 b0, b1, b2, b3;
            ldm_x4(mtb + boffb + np * 16 * 80 + ks * 32, b0, b1, b2, b3);
            Bf[2 * np][ks][0] = b0; Bf[2 * np][ks][1] = b1;
            Bf[2 * np + 1][ks][0] = b2; Bf[2 * np + 1][ks][1] = b3;
        }

    // four independent row-tiles per warp
    const int trow0 = blockIdx.x * 512 + wid * 16 + (lane >> 2);

#pragma unroll
    for (int half = 0; half < 4; half++) {
        const int trow = trow0 + half * 128;
        const bool ok1 = trow < N, ok2 = (trow + 8) < N;
        const __half* ur = g_Uh + (size_t)trow * 32 + (lane & 3) * 2;

        u32 af[2][4];
#pragma unroll
        for (int ks = 0; ks < 2; ks++) {
            af[ks][0] = ok1 ? *(const u32*)(ur + ks * 16)          : 0u;
            af[ks][1] = ok2 ? *(const u32*)(ur + ks * 16 + 8 * 32) : 0u;
            af[ks][2] = ok1 ? *(const u32*)(ur + ks * 16 + 8)      : 0u;
            af[ks][3] = ok2 ? *(const u32*)(ur + ks * 16 + 8 * 32 + 8) : 0u;
        }

        float acc[4][4];
#pragma unroll
        for (int nf = 0; nf < 4; nf++)
#pragma unroll
            for (int q = 0; q < 4; q++) acc[nf][q] = 0.f;

#pragma unroll
        for (int ks = 0; ks < 2; ks++)
#pragma unroll
            for (int nf = 0; nf < 4; nf++)
                mma16816(acc[nf][0], acc[nf][1], acc[nf][2], acc[nf][3],
                         af[ks][0], af[ks][1], af[ks][2], af[ks][3],
                         Bf[nf][ks][0], Bf[nf][ks][1]);

#pragma unroll
        for (int nf = 0; nf < 4; nf++) {
            const int col = nf * 8 + (lane & 3) * 2;
            if (ok1) *(float2*)(out + (size_t)trow * 64 + col) =
                make_float2(acc[nf][0], acc[nf][1]);
            if (ok2) *(float2*)(out + (size_t)(trow + 8) * 64 + col) =
                make_float2(acc[nf][2], acc[nf][3]);
        }
    }
}

// ---------------------------------------------------------------------------
extern "C" void kernel_launch(void* const* d_in, const int* in_sizes, int n_in,
                              void* d_out, int out_size)
{
    const float* x = (const float*)d_in[0];
    const float* W = (const float*)d_in[1];
    const float* b = (const float*)d_in[2];
    float* out = (float*)d_out;

    const int N  = in_sizes[0] / D_IN;
    const int nb = (N + TM - 1) / TM;
    const int np = nb < GRIDP ? nb : GRIDP;

    cudaFuncSetAttribute(pass1_kernel,
                         cudaFuncAttributeMaxDynamicSharedMemorySize, DSM_B);

    dummy1_kernel<<<1, 32>>>();
    dummy2_kernel<<<1, 32>>>();
    wconv_kernel<<<(D_IN * C_OUT + 255) / 256, 256>>>(W);
    pass1_kernel<<<np, THREADS, DSM_B>>>(x, b, out, N, nb);
    reduce_kernel<<<(NPART * 32 + THREADS - 1) / THREADS, THREADS>>>(np, nb);
    pass3_kernel<<<(N + 511) / 512, THREADS>>>(out, N);
}